// round 1
// baseline (speedup 1.0000x reference)
#include <cuda_runtime.h>
#include <math.h>

#define BZ   4
#define QL   512
#define CL   1536
#define KVL  2048
#define E    1024
#define NH   16
#define HD   64
#define MROWS (BZ*QL)   // 2048

#define OUT_K ((size_t)MROWS*E)                       // 2097152
#define OUT_V (OUT_K + (size_t)BZ*KVL*E)              // 10485760

// ---------------- scratch (device globals; no allocations allowed) ----------
__device__ float g_q[MROWS*E];          // Q projection  [2048,1024]
__device__ float g_ctx[MROWS*E];        // attention output [2048,1024]
__device__ float g_wqkvt[E*3*E];        // [k][3072]  (Wq|Wk|Wv transposed)
__device__ float g_wot[E*E];            // [k][1024]  Wo transposed

// ---------------- weight transpose: out[k][n] = W[n][k] ---------------------
__global__ void transpose_w(const float* __restrict__ W, int dst)
{
    __shared__ float tile[32][33];
    float* out;
    int ostride, noff;
    if (dst < 3) { out = g_wqkvt; ostride = 3*E; noff = dst*E; }
    else         { out = g_wot;   ostride = E;   noff = 0;     }

    int k0 = blockIdx.x*32, n0 = blockIdx.y*32;
    int tx = threadIdx.x, ty = threadIdx.y;
    #pragma unroll
    for (int i = 0; i < 32; i += 8)
        tile[ty+i][tx] = W[(size_t)(n0+ty+i)*E + k0 + tx];
    __syncthreads();
    #pragma unroll
    for (int i = 0; i < 32; i += 8)
        out[(size_t)(k0+ty+i)*ostride + noff + n0 + tx] = tile[tx][ty+i];
}

// ---------------- cache copy into output concat layout ----------------------
__global__ void copy_cache(const float4* __restrict__ kc,
                           const float4* __restrict__ vc,
                           float* __restrict__ dout)
{
    const int per_b = CL*E/4;                 // 393216 float4 per batch
    int idx = blockIdx.x*blockDim.x + threadIdx.x;
    if (idx >= BZ*per_b) return;
    int b = idx / per_b, rem = idx - b*per_b;
    float4* outk = (float4*)(dout + OUT_K);
    float4* outv = (float4*)(dout + OUT_V);
    size_t d = (size_t)b*(KVL*E/4) + rem;     // rows [0,CL) of each batch
    outk[d] = kc[idx];
    outv[d] = vc[idx];
}

// ---------------- fused QKV SGEMM: [2048,1024] x [1024,3072] ----------------
// A row-major, BT = g_wqkvt (k-major). BM=BN=128, BK=8, 8x8 per thread.
__global__ __launch_bounds__(256, 2)
void sgemm_qkv(const float* __restrict__ A,
               const float* __restrict__ bq,
               const float* __restrict__ bk,
               const float* __restrict__ bv,
               float* __restrict__ dout)
{
    const int N = 3*E, K = E;
    __shared__ float As[8][128];
    __shared__ float Bs[8][128];

    int bm = blockIdx.y*128, bn = blockIdx.x*128;
    int tid = threadIdx.x;
    int tr = tid >> 4, tc = tid & 15;
    int arow = tid >> 1, acol = (tid & 1)*4;
    int brow = tid >> 5, bcol = (tid & 31)*4;

    const float* Aptr = A + (size_t)(bm + arow)*K + acol;
    const float* Bptr = g_wqkvt + (size_t)brow*N + bn + bcol;

    float acc[8][8];
    #pragma unroll
    for (int i = 0; i < 8; i++)
        #pragma unroll
        for (int j = 0; j < 8; j++) acc[i][j] = 0.f;

    for (int k0 = 0; k0 < K; k0 += 8) {
        float4 av  = *(const float4*)(Aptr + k0);
        float4 bv4 = *(const float4*)(Bptr + (size_t)k0*N);
        As[acol+0][arow] = av.x;
        As[acol+1][arow] = av.y;
        As[acol+2][arow] = av.z;
        As[acol+3][arow] = av.w;
        *(float4*)&Bs[brow][bcol] = bv4;
        __syncthreads();
        #pragma unroll
        for (int kk = 0; kk < 8; kk++) {
            float a[8], b[8];
            *(float4*)&a[0] = *(float4*)&As[kk][tr*8];
            *(float4*)&a[4] = *(float4*)&As[kk][tr*8+4];
            *(float4*)&b[0] = *(float4*)&Bs[kk][tc*8];
            *(float4*)&b[4] = *(float4*)&Bs[kk][tc*8+4];
            #pragma unroll
            for (int i = 0; i < 8; i++)
                #pragma unroll
                for (int j = 0; j < 8; j++)
                    acc[i][j] += a[i]*b[j];
        }
        __syncthreads();
    }

    int seg = bn >> 10;               // 0=Q 1=K 2=V (128-blocks never straddle)
    int nl  = (bn & 1023) + tc*8;     // local column within segment
    int m0  = bm + tr*8;

    if (seg == 0) {
        #pragma unroll
        for (int i = 0; i < 8; i++)
            #pragma unroll
            for (int j = 0; j < 8; j++)
                g_q[(size_t)(m0+i)*E + nl + j] = acc[i][j] + bq[nl+j];
    } else {
        float* dst = dout + ((seg == 1) ? OUT_K : OUT_V);
        const float* bias = (seg == 1) ? bk : bv;
        #pragma unroll
        for (int i = 0; i < 8; i++) {
            int m = m0 + i;
            int b_ = m >> 9, t = m & 511;
            float* row = dst + ((size_t)(b_*KVL) + CL + t)*E;
            #pragma unroll
            for (int j = 0; j < 8; j++)
                row[nl+j] = acc[i][j] + bias[nl+j];
        }
    }
}

// ---------------- output projection SGEMM: g_ctx x g_wot --------------------
__global__ __launch_bounds__(256, 2)
void sgemm_out(const float* __restrict__ bo, float* __restrict__ dout)
{
    const int N = E, K = E;
    __shared__ float As[8][128];
    __shared__ float Bs[8][128];

    int bm = blockIdx.y*128, bn = blockIdx.x*128;
    int tid = threadIdx.x;
    int tr = tid >> 4, tc = tid & 15;
    int arow = tid >> 1, acol = (tid & 1)*4;
    int brow = tid >> 5, bcol = (tid & 31)*4;

    const float* Aptr = g_ctx + (size_t)(bm + arow)*K + acol;
    const float* Bptr = g_wot + (size_t)brow*N + bn + bcol;

    float acc[8][8];
    #pragma unroll
    for (int i = 0; i < 8; i++)
        #pragma unroll
        for (int j = 0; j < 8; j++) acc[i][j] = 0.f;

    for (int k0 = 0; k0 < K; k0 += 8) {
        float4 av  = *(const float4*)(Aptr + k0);
        float4 bv4 = *(const float4*)(Bptr + (size_t)k0*N);
        As[acol+0][arow] = av.x;
        As[acol+1][arow] = av.y;
        As[acol+2][arow] = av.z;
        As[acol+3][arow] = av.w;
        *(float4*)&Bs[brow][bcol] = bv4;
        __syncthreads();
        #pragma unroll
        for (int kk = 0; kk < 8; kk++) {
            float a[8], b[8];
            *(float4*)&a[0] = *(float4*)&As[kk][tr*8];
            *(float4*)&a[4] = *(float4*)&As[kk][tr*8+4];
            *(float4*)&b[0] = *(float4*)&Bs[kk][tc*8];
            *(float4*)&b[4] = *(float4*)&Bs[kk][tc*8+4];
            #pragma unroll
            for (int i = 0; i < 8; i++)
                #pragma unroll
                for (int j = 0; j < 8; j++)
                    acc[i][j] += a[i]*b[j];
        }
        __syncthreads();
    }

    #pragma unroll
    for (int i = 0; i < 8; i++)
        #pragma unroll
        for (int j = 0; j < 8; j++)
            dout[(size_t)(bm+tr*8+i)*E + bn + tc*8 + j] = acc[i][j] + bo[bn+tc*8+j];
}

// ---------------- fused flash attention (fp32) ------------------------------
// One block = (batch b, head h, 64-row Q tile). Online softmax over 64-col KV
// tiles. SMEM: Qs, Ks, Vs (48KB). P reuses Ks between extra barriers.
// XOR swizzle: element (r,d) stored at [r][d ^ (r&31)] -> conflict-free
// column-ish reads.
#define SW(r,d) (((unsigned)(d)) ^ ((unsigned)(r) & 31u))

__global__ __launch_bounds__(256)
void attn_kernel(const float* __restrict__ amask, float* __restrict__ dout)
{
    int qt = blockIdx.x, h = blockIdx.y, b = blockIdx.z;
    __shared__ float Qs[64][64];
    __shared__ float Ks[64][64];   // also reused as P
    __shared__ float Vs[64][64];

    const float* kall = dout + OUT_K;
    const float* vall = dout + OUT_V;

    int tid = threadIdx.x;
    int tr = tid >> 4, tc = tid & 15;
    int tr4 = tr*4, tc4 = tc*4;

    // load Q tile (swizzled)
    for (int i = tid; i < 64*64; i += 256) {
        int r = i >> 6, d = i & 63;
        Qs[r][SW(r,d)] = g_q[((size_t)(b*QL + qt*64 + r))*E + h*HD + d];
    }

    float m_i[4], l_i[4], O[4][4];
    #pragma unroll
    for (int i = 0; i < 4; i++) {
        m_i[i] = -1e30f; l_i[i] = 0.f;
        #pragma unroll
        for (int j = 0; j < 4; j++) O[i][j] = 0.f;
    }

    int row_abs0 = CL + qt*64 + tr4;
    int nkt = 25 + qt;                       // tiles 0..24+qt are (partially) visible

    for (int kt = 0; kt < nkt; kt++) {
        int c0 = kt*64;
        for (int i = tid; i < 64*64; i += 256) {
            int r = i >> 6, d = i & 63;
            size_t g = ((size_t)(b*KVL + c0 + r))*E + h*HD + d;
            Ks[r][SW(r,d)] = kall[g];
            Vs[r][SW(r,d)] = vall[g];
        }
        __syncthreads();

        // S = Q K^T
        float S[4][4];
        #pragma unroll
        for (int i = 0; i < 4; i++)
            #pragma unroll
            for (int j = 0; j < 4; j++) S[i][j] = 0.f;
        #pragma unroll 8
        for (int d = 0; d < 64; d++) {
            float a[4], bb[4];
            #pragma unroll
            for (int i = 0; i < 4; i++) a[i]  = Qs[tr4+i][SW(tr4+i, d)];
            #pragma unroll
            for (int j = 0; j < 4; j++) bb[j] = Ks[tc4+j][SW(tc4+j, d)];
            #pragma unroll
            for (int i = 0; i < 4; i++)
                #pragma unroll
                for (int j = 0; j < 4; j++)
                    S[i][j] += a[i]*bb[j];
        }

        // scale + masks
        #pragma unroll
        for (int i = 0; i < 4; i++)
            #pragma unroll
            for (int j = 0; j < 4; j++) {
                int col = c0 + tc4 + j;
                float s = S[i][j]*0.125f + amask[b*KVL + col];
                if (col > row_abs0 + i) s = -1e30f;
                S[i][j] = s;
            }

        // online softmax (row reductions across the 16-lane tc group)
        float mt[4], rs[4], corr[4];
        #pragma unroll
        for (int i = 0; i < 4; i++) {
            float m = S[i][0];
            #pragma unroll
            for (int j = 1; j < 4; j++) m = fmaxf(m, S[i][j]);
            #pragma unroll
            for (int s = 1; s < 16; s <<= 1)
                m = fmaxf(m, __shfl_xor_sync(0xffffffffu, m, s));
            mt[i] = m;
        }
        #pragma unroll
        for (int i = 0; i < 4; i++) {
            float mn = fmaxf(m_i[i], mt[i]);
            corr[i] = __expf(m_i[i] - mn);
            m_i[i] = mn;
        }
        #pragma unroll
        for (int i = 0; i < 4; i++) {
            float r = 0.f;
            #pragma unroll
            for (int j = 0; j < 4; j++) {
                float p = __expf(S[i][j] - m_i[i]);
                S[i][j] = p;
                r += p;
            }
            #pragma unroll
            for (int s = 1; s < 16; s <<= 1)
                r += __shfl_xor_sync(0xffffffffu, r, s);
            rs[i] = r;
        }
        #pragma unroll
        for (int i = 0; i < 4; i++) {
            l_i[i] = l_i[i]*corr[i] + rs[i];
            #pragma unroll
            for (int j = 0; j < 4; j++) O[i][j] *= corr[i];
        }

        __syncthreads();                     // everyone done reading Ks
        #pragma unroll
        for (int i = 0; i < 4; i++)
            #pragma unroll
            for (int j = 0; j < 4; j++)
                Ks[tr4+i][SW(tr4+i, tc4+j)] = S[i][j];   // P -> Ks
        __syncthreads();

        // O += P V
        #pragma unroll 8
        for (int c = 0; c < 64; c++) {
            float a[4], bb[4];
            #pragma unroll
            for (int i = 0; i < 4; i++) a[i]  = Ks[tr4+i][SW(tr4+i, c)];
            #pragma unroll
            for (int j = 0; j < 4; j++) bb[j] = Vs[c][SW(c, tc4+j)];
            #pragma unroll
            for (int i = 0; i < 4; i++)
                #pragma unroll
                for (int j = 0; j < 4; j++)
                    O[i][j] += a[i]*bb[j];
        }
        __syncthreads();                     // before next tile load
    }

    #pragma unroll
    for (int i = 0; i < 4; i++) {
        float inv = 1.f / l_i[i];
        #pragma unroll
        for (int j = 0; j < 4; j++)
            g_ctx[((size_t)(b*QL + qt*64 + tr4 + i))*E + h*HD + tc4 + j] = O[i][j]*inv;
    }
}

// ---------------- launch ----------------------------------------------------
extern "C" void kernel_launch(void* const* d_in, const int* in_sizes, int n_in,
                              void* d_out, int out_size)
{
    const float* X     = (const float*)d_in[0];
    const float* amask = (const float*)d_in[1];
    const float* kc    = (const float*)d_in[2];
    const float* vc    = (const float*)d_in[3];
    const float* Wq    = (const float*)d_in[4];
    const float* bq    = (const float*)d_in[5];
    const float* Wk    = (const float*)d_in[6];
    const float* bk    = (const float*)d_in[7];
    const float* Wv    = (const float*)d_in[8];
    const float* bv    = (const float*)d_in[9];
    const float* Wo    = (const float*)d_in[10];
    const float* bo    = (const float*)d_in[11];
    float* out = (float*)d_out;

    dim3 tb(32, 8), tg(32, 32);
    transpose_w<<<tg, tb>>>(Wq, 0);
    transpose_w<<<tg, tb>>>(Wk, 1);
    transpose_w<<<tg, tb>>>(Wv, 2);
    transpose_w<<<tg, tb>>>(Wo, 3);

    {
        int total = BZ*CL*E/4;
        copy_cache<<<(total + 255)/256, 256>>>((const float4*)kc, (const float4*)vc, out);
    }

    {
        dim3 grid(3*E/128, MROWS/128);       // 24 x 16
        sgemm_qkv<<<grid, 256>>>(X, bq, bk, bv, out);
    }

    {
        dim3 grid(QL/64, NH, BZ);            // 8 x 16 x 4
        attn_kernel<<<grid, 256>>>(amask, out);
    }

    {
        dim3 grid(E/128, MROWS/128);         // 8 x 16
        sgemm_out<<<grid, 256>>>(bo, out);
    }
}

// round 2
// speedup vs baseline: 2.7951x; 2.7951x over previous
#include <cuda_runtime.h>
#include <math.h>

#define BZ   4
#define QL   512
#define CL   1536
#define KVL  2048
#define E    1024
#define NH   16
#define HD   64
#define MROWS (BZ*QL)   // 2048

#define OUT_K ((size_t)MROWS*E)                       // 2097152
#define OUT_V (OUT_K + (size_t)BZ*KVL*E)              // 10485760

// ---------------- scratch ----------------------------------------------------
__device__ float g_q[MROWS*E];          // scaled Q projection  [2048,1024]
__device__ float g_ctx[MROWS*E];        // attention output     [2048,1024]

// ---------------- helpers ----------------------------------------------------
__device__ __forceinline__ unsigned f2tf(float f) {
    unsigned u;
    asm("cvt.rna.tf32.f32 %0, %1;" : "=r"(u) : "f"(f));
    return u;
}

__device__ __forceinline__ void mma8(float* c,
                                     unsigned a0, unsigned a1, unsigned a2, unsigned a3,
                                     unsigned b0, unsigned b1)
{
    asm volatile(
        "mma.sync.aligned.m16n8k8.row.col.f32.tf32.tf32.f32 "
        "{%0,%1,%2,%3}, {%4,%5,%6,%7}, {%8,%9}, {%0,%1,%2,%3};\n"
        : "+f"(c[0]), "+f"(c[1]), "+f"(c[2]), "+f"(c[3])
        : "r"(a0), "r"(a1), "r"(a2), "r"(a3), "r"(b0), "r"(b1));
}

// ---------------- cache copy into output concat layout ----------------------
__global__ void copy_cache(const float4* __restrict__ kc,
                           const float4* __restrict__ vc,
                           float* __restrict__ dout)
{
    const int per_b = CL*E/4;
    int idx = blockIdx.x*blockDim.x + threadIdx.x;
    if (idx >= BZ*per_b) return;
    int b = idx / per_b, rem = idx - b*per_b;
    float4* outk = (float4*)(dout + OUT_K);
    float4* outv = (float4*)(dout + OUT_V);
    size_t d = (size_t)b*(KVL*E/4) + rem;
    outk[d] = kc[idx];
    outv[d] = vc[idx];
}

// ---------------- tf32 tensor-core GEMM: QKV projection ---------------------
// C = X @ W^T + b.  X row-major [2048,1024], W [n][k] (k-contiguous = col-major B).
// BM=BN=128, BK=32, 512 threads, warp grid 4x4, warp tile 32x32.
#define GS 36   // smem stride (words); bank = (4*row + k) % 32 -> conflict-free frags

__global__ __launch_bounds__(512)
void gemm_qkv(const float* __restrict__ X,
              const float* __restrict__ Wq, const float* __restrict__ bq,
              const float* __restrict__ Wk, const float* __restrict__ bk,
              const float* __restrict__ Wv, const float* __restrict__ bv,
              float* __restrict__ dout)
{
    __shared__ unsigned As[128*GS];
    __shared__ unsigned Bs[128*GS];

    int bn = blockIdx.x*128, bm = blockIdx.y*128;
    const float* W; const float* bias;
    if (bn < E)        { W = Wq; bias = bq; }
    else if (bn < 2*E) { W = Wk; bias = bk; }
    else               { W = Wv; bias = bv; }
    int nloc = bn & (E-1);

    int tid  = threadIdx.x;
    int warp = tid >> 5, lane = tid & 31, g = lane >> 2, tig = lane & 3;
    int wm = (warp >> 2)*32, wn = (warp & 3)*32;

    int lrow = tid >> 3;          // 0..63
    int lc4  = (tid & 7)*4;       // 0..28

    const float* Ap = X + (size_t)(bm + lrow)*E + lc4;
    const float* Bp = W + (size_t)(nloc + lrow)*E + lc4;

    float4 pa0 = *(const float4*)(Ap);
    float4 pa1 = *(const float4*)(Ap + (size_t)64*E);
    float4 pb0 = *(const float4*)(Bp);
    float4 pb1 = *(const float4*)(Bp + (size_t)64*E);

    float acc[2][4][4];
    #pragma unroll
    for (int mt = 0; mt < 2; mt++)
        #pragma unroll
        for (int nt = 0; nt < 4; nt++)
            #pragma unroll
            for (int i = 0; i < 4; i++) acc[mt][nt][i] = 0.f;

    for (int k0 = 0; k0 < E; k0 += 32) {
        unsigned4_t: ;
        { uint4 u;
          u.x=f2tf(pa0.x); u.y=f2tf(pa0.y); u.z=f2tf(pa0.z); u.w=f2tf(pa0.w);
          *(uint4*)&As[lrow*GS + lc4] = u;
          u.x=f2tf(pa1.x); u.y=f2tf(pa1.y); u.z=f2tf(pa1.z); u.w=f2tf(pa1.w);
          *(uint4*)&As[(lrow+64)*GS + lc4] = u;
          u.x=f2tf(pb0.x); u.y=f2tf(pb0.y); u.z=f2tf(pb0.z); u.w=f2tf(pb0.w);
          *(uint4*)&Bs[lrow*GS + lc4] = u;
          u.x=f2tf(pb1.x); u.y=f2tf(pb1.y); u.z=f2tf(pb1.z); u.w=f2tf(pb1.w);
          *(uint4*)&Bs[(lrow+64)*GS + lc4] = u;
        }
        __syncthreads();
        if (k0 + 32 < E) {
            pa0 = *(const float4*)(Ap + k0 + 32);
            pa1 = *(const float4*)(Ap + k0 + 32 + (size_t)64*E);
            pb0 = *(const float4*)(Bp + k0 + 32);
            pb1 = *(const float4*)(Bp + k0 + 32 + (size_t)64*E);
        }
        #pragma unroll
        for (int kc = 0; kc < 4; kc++) {
            int kb = kc*8;
            unsigned af[2][4], bf[4][2];
            #pragma unroll
            for (int mt = 0; mt < 2; mt++) {
                int r = wm + mt*16;
                af[mt][0] = As[(r+g  )*GS + kb + tig];
                af[mt][1] = As[(r+g+8)*GS + kb + tig];
                af[mt][2] = As[(r+g  )*GS + kb + tig + 4];
                af[mt][3] = As[(r+g+8)*GS + kb + tig + 4];
            }
            #pragma unroll
            for (int nt = 0; nt < 4; nt++) {
                int cidx = wn + nt*8 + g;
                bf[nt][0] = Bs[cidx*GS + kb + tig];
                bf[nt][1] = Bs[cidx*GS + kb + tig + 4];
            }
            #pragma unroll
            for (int mt = 0; mt < 2; mt++)
                #pragma unroll
                for (int nt = 0; nt < 4; nt++)
                    mma8(acc[mt][nt], af[mt][0], af[mt][1], af[mt][2], af[mt][3],
                         bf[nt][0], bf[nt][1]);
        }
        __syncthreads();
    }

    // epilogue: bias + scatter.  Q -> g_q (pre-scaled by 1/8 later in attn load).
    #pragma unroll
    for (int mt = 0; mt < 2; mt++) {
        int m = bm + wm + mt*16 + g;
        #pragma unroll
        for (int nt = 0; nt < 4; nt++) {
            int nl = nloc + wn + nt*8 + 2*tig;
            float bv0 = bias[nl], bv1 = bias[nl+1];
            float2 r0 = make_float2(acc[mt][nt][0] + bv0, acc[mt][nt][1] + bv1);
            float2 r1 = make_float2(acc[mt][nt][2] + bv0, acc[mt][nt][3] + bv1);
            if (bn < E) {
                *(float2*)&g_q[(size_t)m*E + nl]     = r0;
                *(float2*)&g_q[(size_t)(m+8)*E + nl] = r1;
            } else {
                float* base = dout + (bn < 2*E ? OUT_K : OUT_V);
                int b0_ = m >> 9,     t0 = m & 511;
                int b1_ = (m+8) >> 9, t1 = (m+8) & 511;
                *(float2*)&base[((size_t)(b0_*KVL) + CL + t0)*E + nl] = r0;
                *(float2*)&base[((size_t)(b1_*KVL) + CL + t1)*E + nl] = r1;
            }
        }
    }
}

// ---------------- tf32 tensor-core GEMM: output projection -------------------
__global__ __launch_bounds__(512)
void gemm_out(const float* __restrict__ Wo, const float* __restrict__ bo,
              float* __restrict__ dout)
{
    __shared__ unsigned As[128*GS];
    __shared__ unsigned Bs[128*GS];

    int bn = blockIdx.x*128, bm = blockIdx.y*128;
    int tid  = threadIdx.x;
    int warp = tid >> 5, lane = tid & 31, g = lane >> 2, tig = lane & 3;
    int wm = (warp >> 2)*32, wn = (warp & 3)*32;
    int lrow = tid >> 3, lc4 = (tid & 7)*4;

    const float* Ap = g_ctx + (size_t)(bm + lrow)*E + lc4;
    const float* Bp = Wo    + (size_t)(bn + lrow)*E + lc4;

    float4 pa0 = *(const float4*)(Ap);
    float4 pa1 = *(const float4*)(Ap + (size_t)64*E);
    float4 pb0 = *(const float4*)(Bp);
    float4 pb1 = *(const float4*)(Bp + (size_t)64*E);

    float acc[2][4][4];
    #pragma unroll
    for (int mt = 0; mt < 2; mt++)
        #pragma unroll
        for (int nt = 0; nt < 4; nt++)
            #pragma unroll
            for (int i = 0; i < 4; i++) acc[mt][nt][i] = 0.f;

    for (int k0 = 0; k0 < E; k0 += 32) {
        { uint4 u;
          u.x=f2tf(pa0.x); u.y=f2tf(pa0.y); u.z=f2tf(pa0.z); u.w=f2tf(pa0.w);
          *(uint4*)&As[lrow*GS + lc4] = u;
          u.x=f2tf(pa1.x); u.y=f2tf(pa1.y); u.z=f2tf(pa1.z); u.w=f2tf(pa1.w);
          *(uint4*)&As[(lrow+64)*GS + lc4] = u;
          u.x=f2tf(pb0.x); u.y=f2tf(pb0.y); u.z=f2tf(pb0.z); u.w=f2tf(pb0.w);
          *(uint4*)&Bs[lrow*GS + lc4] = u;
          u.x=f2tf(pb1.x); u.y=f2tf(pb1.y); u.z=f2tf(pb1.z); u.w=f2tf(pb1.w);
          *(uint4*)&Bs[(lrow+64)*GS + lc4] = u;
        }
        __syncthreads();
        if (k0 + 32 < E) {
            pa0 = *(const float4*)(Ap + k0 + 32);
            pa1 = *(const float4*)(Ap + k0 + 32 + (size_t)64*E);
            pb0 = *(const float4*)(Bp + k0 + 32);
            pb1 = *(const float4*)(Bp + k0 + 32 + (size_t)64*E);
        }
        #pragma unroll
        for (int kc = 0; kc < 4; kc++) {
            int kb = kc*8;
            unsigned af[2][4], bf[4][2];
            #pragma unroll
            for (int mt = 0; mt < 2; mt++) {
                int r = wm + mt*16;
                af[mt][0] = As[(r+g  )*GS + kb + tig];
                af[mt][1] = As[(r+g+8)*GS + kb + tig];
                af[mt][2] = As[(r+g  )*GS + kb + tig + 4];
                af[mt][3] = As[(r+g+8)*GS + kb + tig + 4];
            }
            #pragma unroll
            for (int nt = 0; nt < 4; nt++) {
                int cidx = wn + nt*8 + g;
                bf[nt][0] = Bs[cidx*GS + kb + tig];
                bf[nt][1] = Bs[cidx*GS + kb + tig + 4];
            }
            #pragma unroll
            for (int mt = 0; mt < 2; mt++)
                #pragma unroll
                for (int nt = 0; nt < 4; nt++)
                    mma8(acc[mt][nt], af[mt][0], af[mt][1], af[mt][2], af[mt][3],
                         bf[nt][0], bf[nt][1]);
        }
        __syncthreads();
    }

    #pragma unroll
    for (int mt = 0; mt < 2; mt++) {
        int m = bm + wm + mt*16 + g;
        #pragma unroll
        for (int nt = 0; nt < 4; nt++) {
            int n = bn + wn + nt*8 + 2*tig;
            float bv0 = bo[n], bv1 = bo[n+1];
            *(float2*)&dout[(size_t)m*E + n] =
                make_float2(acc[mt][nt][0] + bv0, acc[mt][nt][1] + bv1);
            *(float2*)&dout[(size_t)(m+8)*E + n] =
                make_float2(acc[mt][nt][2] + bv0, acc[mt][nt][3] + bv1);
        }
    }
}

// ---------------- flash attention, tf32 tensor cores ------------------------
// Block = (qt, h, b), 128 threads (4 warps), each warp owns 16 q-rows.
// SMEM 48KB exactly: Qs, KPs (K then P), Vs — XOR swizzles per access pattern.
#define SWK(r,d) ((d) ^ ((((unsigned)(r))&7u)<<2))
#define SWV(r,d) ((d) ^ ((((unsigned)(r))&3u)<<3))

__global__ __launch_bounds__(128)
void attn(const float* __restrict__ amask, float* __restrict__ dout)
{
    __shared__ unsigned Qs[64*64];
    __shared__ unsigned KPs[64*64];
    __shared__ unsigned Vs[64*64];

    int qt = blockIdx.x, h = blockIdx.y, b = blockIdx.z;
    const float* kall = dout + OUT_K;
    const float* vall = dout + OUT_V;

    int tid  = threadIdx.x;
    int warp = tid >> 5, lane = tid & 31, g = lane >> 2, tig = lane & 3;
    int m0 = warp*16;

    // ---- load Q tile (scale 1/8 folded in) ----
    {
        int row = tid >> 4, d4 = (tid & 15)*4;
        #pragma unroll
        for (int r = 0; r < 8; r++) {
            int rr = row + r*8;
            float4 q4 = *(const float4*)&g_q[((size_t)(b*QL + qt*64 + rr))*E + h*HD + d4];
            uint4 u;
            u.x = f2tf(q4.x*0.125f); u.y = f2tf(q4.y*0.125f);
            u.z = f2tf(q4.z*0.125f); u.w = f2tf(q4.w*0.125f);
            *(uint4*)&Qs[rr*64 + SWK(rr, d4)] = u;
        }
    }
    __syncthreads();

    // ---- Q fragments persistent in regs ----
    unsigned qf[8][4];
    #pragma unroll
    for (int kc = 0; kc < 8; kc++) {
        int kb = kc*8;
        qf[kc][0] = Qs[(m0+g  )*64 + SWK(m0+g,   kb+tig)];
        qf[kc][1] = Qs[(m0+g+8)*64 + SWK(m0+g+8, kb+tig)];
        qf[kc][2] = Qs[(m0+g  )*64 + SWK(m0+g,   kb+tig+4)];
        qf[kc][3] = Qs[(m0+g+8)*64 + SWK(m0+g+8, kb+tig+4)];
    }

    float O[8][4];
    #pragma unroll
    for (int nt = 0; nt < 8; nt++)
        #pragma unroll
        for (int i = 0; i < 4; i++) O[nt][i] = 0.f;
    float mi0 = -1e30f, mi1 = -1e30f, li0 = 0.f, li1 = 0.f;

    int nkt = 25 + qt;
    for (int kt = 0; kt < nkt; kt++) {
        int c0 = kt*64;
        // ---- load K,V tile ----
        {
            int row = tid >> 4, d4 = (tid & 15)*4;
            #pragma unroll
            for (int r = 0; r < 8; r++) {
                int rr = row + r*8;
                size_t gidx = ((size_t)(b*KVL + c0 + rr))*E + h*HD + d4;
                float4 k4 = *(const float4*)&kall[gidx];
                float4 v4 = *(const float4*)&vall[gidx];
                uint4 u;
                u.x = f2tf(k4.x); u.y = f2tf(k4.y); u.z = f2tf(k4.z); u.w = f2tf(k4.w);
                *(uint4*)&KPs[rr*64 + SWK(rr, d4)] = u;
                u.x = f2tf(v4.x); u.y = f2tf(v4.y); u.z = f2tf(v4.z); u.w = f2tf(v4.w);
                *(uint4*)&Vs[rr*64 + SWV(rr, d4)] = u;
            }
        }
        __syncthreads();

        // ---- S = (Q/8) K^T ----
        float s[8][4];
        #pragma unroll
        for (int nt = 0; nt < 8; nt++)
            #pragma unroll
            for (int i = 0; i < 4; i++) s[nt][i] = 0.f;
        #pragma unroll
        for (int kc = 0; kc < 8; kc++) {
            int kb = kc*8;
            #pragma unroll
            for (int nt = 0; nt < 8; nt++) {
                int col = nt*8 + g;
                unsigned b0 = KPs[col*64 + SWK(col, kb+tig)];
                unsigned b1 = KPs[col*64 + SWK(col, kb+tig+4)];
                mma8(s[nt], qf[kc][0], qf[kc][1], qf[kc][2], qf[kc][3], b0, b1);
            }
        }

        // ---- mask + online softmax ----
        const float* am = amask + (size_t)b*KVL + c0;
        bool last = (kt == nkt-1);
        #pragma unroll
        for (int nt = 0; nt < 8; nt++) {
            int j0 = nt*8 + 2*tig, j1 = j0 + 1;
            float a0 = __ldg(am + j0), a1 = __ldg(am + j1);
            s[nt][0] += a0; s[nt][1] += a1; s[nt][2] += a0; s[nt][3] += a1;
            if (last) {
                int r0 = m0 + g, r1 = r0 + 8;
                if (j0 > r0) s[nt][0] = -1e30f;
                if (j1 > r0) s[nt][1] = -1e30f;
                if (j0 > r1) s[nt][2] = -1e30f;
                if (j1 > r1) s[nt][3] = -1e30f;
            }
        }

        float mx0 = -1e30f, mx1 = -1e30f;
        #pragma unroll
        for (int nt = 0; nt < 8; nt++) {
            mx0 = fmaxf(mx0, fmaxf(s[nt][0], s[nt][1]));
            mx1 = fmaxf(mx1, fmaxf(s[nt][2], s[nt][3]));
        }
        mx0 = fmaxf(mx0, __shfl_xor_sync(0xffffffffu, mx0, 1));
        mx0 = fmaxf(mx0, __shfl_xor_sync(0xffffffffu, mx0, 2));
        mx1 = fmaxf(mx1, __shfl_xor_sync(0xffffffffu, mx1, 1));
        mx1 = fmaxf(mx1, __shfl_xor_sync(0xffffffffu, mx1, 2));

        float mn0 = fmaxf(mi0, mx0), mn1 = fmaxf(mi1, mx1);
        float cor0 = __expf(mi0 - mn0), cor1 = __expf(mi1 - mn1);
        mi0 = mn0; mi1 = mn1;

        float sum0 = 0.f, sum1 = 0.f;
        #pragma unroll
        for (int nt = 0; nt < 8; nt++) {
            s[nt][0] = __expf(s[nt][0] - mn0); sum0 += s[nt][0];
            s[nt][1] = __expf(s[nt][1] - mn0); sum0 += s[nt][1];
            s[nt][2] = __expf(s[nt][2] - mn1); sum1 += s[nt][2];
            s[nt][3] = __expf(s[nt][3] - mn1); sum1 += s[nt][3];
        }
        sum0 += __shfl_xor_sync(0xffffffffu, sum0, 1);
        sum0 += __shfl_xor_sync(0xffffffffu, sum0, 2);
        sum1 += __shfl_xor_sync(0xffffffffu, sum1, 1);
        sum1 += __shfl_xor_sync(0xffffffffu, sum1, 2);
        li0 = li0*cor0 + sum0;
        li1 = li1*cor1 + sum1;
        #pragma unroll
        for (int nt = 0; nt < 8; nt++) {
            O[nt][0] *= cor0; O[nt][1] *= cor0;
            O[nt][2] *= cor1; O[nt][3] *= cor1;
        }

        __syncthreads();   // all warps done reading K from KPs

        // ---- P -> KPs (tf32) ----
        #pragma unroll
        for (int nt = 0; nt < 8; nt++) {
            int j0 = nt*8 + 2*tig;
            int r0 = m0 + g, r1 = r0 + 8;
            uint2 p0; p0.x = f2tf(s[nt][0]); p0.y = f2tf(s[nt][1]);
            uint2 p1; p1.x = f2tf(s[nt][2]); p1.y = f2tf(s[nt][3]);
            *(uint2*)&KPs[r0*64 + SWK(r0, j0)] = p0;
            *(uint2*)&KPs[r1*64 + SWK(r1, j0)] = p1;
        }
        __syncthreads();

        // ---- O += P V ----
        #pragma unroll
        for (int kc = 0; kc < 8; kc++) {
            int kb = kc*8;
            unsigned p0 = KPs[(m0+g  )*64 + SWK(m0+g,   kb+tig)];
            unsigned p1 = KPs[(m0+g+8)*64 + SWK(m0+g+8, kb+tig)];
            unsigned p2 = KPs[(m0+g  )*64 + SWK(m0+g,   kb+tig+4)];
            unsigned p3 = KPs[(m0+g+8)*64 + SWK(m0+g+8, kb+tig+4)];
            #pragma unroll
            for (int nt = 0; nt < 8; nt++) {
                int dcol = nt*8 + g;
                unsigned b0 = Vs[(kb+tig  )*64 + SWV(kb+tig,   dcol)];
                unsigned b1 = Vs[(kb+tig+4)*64 + SWV(kb+tig+4, dcol)];
                mma8(O[nt], p0, p1, p2, p3, b0, b1);
            }
        }
        __syncthreads();   // before next tile overwrites KPs/Vs
    }

    // ---- write ctx ----
    float inv0 = 1.f/li0, inv1 = 1.f/li1;
    int r0 = b*QL + qt*64 + m0 + g;
    #pragma unroll
    for (int nt = 0; nt < 8; nt++) {
        int col = h*HD + nt*8 + 2*tig;
        *(float2*)&g_ctx[(size_t)r0*E + col] =
            make_float2(O[nt][0]*inv0, O[nt][1]*inv0);
        *(float2*)&g_ctx[(size_t)(r0+8)*E + col] =
            make_float2(O[nt][2]*inv1, O[nt][3]*inv1);
    }
}

// ---------------- launch ----------------------------------------------------
extern "C" void kernel_launch(void* const* d_in, const int* in_sizes, int n_in,
                              void* d_out, int out_size)
{
    const float* X     = (const float*)d_in[0];
    const float* amask = (const float*)d_in[1];
    const float* kc    = (const float*)d_in[2];
    const float* vc    = (const float*)d_in[3];
    const float* Wq    = (const float*)d_in[4];
    const float* bq    = (const float*)d_in[5];
    const float* Wk    = (const float*)d_in[6];
    const float* bk    = (const float*)d_in[7];
    const float* Wv    = (const float*)d_in[8];
    const float* bv    = (const float*)d_in[9];
    const float* Wo    = (const float*)d_in[10];
    const float* bo    = (const float*)d_in[11];
    float* out = (float*)d_out;

    {
        int total = BZ*CL*E/4;
        copy_cache<<<(total + 255)/256, 256>>>((const float4*)kc, (const float4*)vc, out);
    }
    {
        dim3 grid(3*E/128, MROWS/128);       // 24 x 16
        gemm_qkv<<<grid, 512>>>(X, Wq, bq, Wk, bk, Wv, bv, out);
    }
    {
        dim3 grid(QL/64, NH, BZ);            // 8 x 16 x 4
        attn<<<grid, 128>>>(amask, out);
    }
    {
        dim3 grid(E/128, MROWS/128);         // 8 x 16
        gemm_out<<<grid, 512>>>(Wo, bo, out);
    }
}

// round 6
// speedup vs baseline: 3.6452x; 1.3041x over previous
#include <cuda_runtime.h>
#include <math.h>

#define BZ   4
#define QL   512
#define CL   1536
#define KVL  2048
#define E    1024
#define NH   16
#define HD   64
#define MROWS (BZ*QL)   // 2048

#define OUT_K ((size_t)MROWS*E)                       // 2097152
#define OUT_V (OUT_K + (size_t)BZ*KVL*E)              // 10485760

// ---------------- scratch (tf32 stored as u32) -------------------------------
__device__ unsigned g_xt [MROWS*E];       // X  tf32
__device__ unsigned g_wqt[E*E];           // Wq tf32 [n][k]
__device__ unsigned g_wkt[E*E];
__device__ unsigned g_wvt[E*E];
__device__ unsigned g_wot[E*E];
__device__ unsigned g_q  [MROWS*E];       // Q proj, tf32, pre-scaled by 1/8
__device__ unsigned g_ctx[MROWS*E];       // attention ctx, tf32
__device__ unsigned g_kt [(size_t)BZ*KVL*E];  // full K (cache+new), tf32
__device__ unsigned g_vt [(size_t)BZ*KVL*E];  // full V, tf32

// ---------------- helpers ----------------------------------------------------
__device__ __forceinline__ unsigned f2tf(float f) {
    unsigned u;
    asm("cvt.rna.tf32.f32 %0, %1;" : "=r"(u) : "f"(f));
    return u;
}

__device__ __forceinline__ void mma8(float* c,
                                     unsigned a0, unsigned a1, unsigned a2, unsigned a3,
                                     unsigned b0, unsigned b1)
{
    asm volatile(
        "mma.sync.aligned.m16n8k8.row.col.f32.tf32.tf32.f32 "
        "{%0,%1,%2,%3}, {%4,%5,%6,%7}, {%8,%9}, {%0,%1,%2,%3};\n"
        : "+f"(c[0]), "+f"(c[1]), "+f"(c[2]), "+f"(c[3])
        : "r"(a0), "r"(a1), "r"(a2), "r"(a3), "r"(b0), "r"(b1));
}

#define CP16(dst, src) \
    asm volatile("cp.async.cg.shared.global [%0], [%1], 16;\n" \
                 :: "r"(dst), "l"(src))
#define CPCOMMIT() asm volatile("cp.async.commit_group;\n" ::: "memory")
#define CPWAIT(n)  asm volatile("cp.async.wait_group %0;\n" :: "n"(n) : "memory")

// ---------------- convert inputs to tf32 -------------------------------------
__global__ void convert_tf32(const float4* __restrict__ X,
                             const float4* __restrict__ Wq,
                             const float4* __restrict__ Wk,
                             const float4* __restrict__ Wv,
                             const float4* __restrict__ Wo)
{
    int i = blockIdx.x*256 + threadIdx.x;
    const float4* src; uint4* dst; int off;
    if (i < 524288)       { src = X;  dst = (uint4*)g_xt;  off = i; }
    else if (i < 786432)  { src = Wq; dst = (uint4*)g_wqt; off = i - 524288; }
    else if (i < 1048576) { src = Wk; dst = (uint4*)g_wkt; off = i - 786432; }
    else if (i < 1310720) { src = Wv; dst = (uint4*)g_wvt; off = i - 1048576; }
    else                  { src = Wo; dst = (uint4*)g_wot; off = i - 1310720; }
    float4 v = src[off];
    uint4 u;
    u.x = f2tf(v.x); u.y = f2tf(v.y); u.z = f2tf(v.z); u.w = f2tf(v.w);
    dst[off] = u;
}

// ---------------- cache copy: f32 to dout + tf32 to g_kt/g_vt ----------------
__global__ void copy_cache(const float4* __restrict__ kc,
                           const float4* __restrict__ vc,
                           float* __restrict__ dout)
{
    const int per_b = CL*E/4;
    int idx = blockIdx.x*blockDim.x + threadIdx.x;
    if (idx >= BZ*per_b) return;
    int b = idx / per_b, rem = idx - b*per_b;
    size_t d = (size_t)b*(KVL*E/4) + rem;
    float4 k4 = kc[idx], v4 = vc[idx];
    ((float4*)(dout + OUT_K))[d] = k4;
    ((float4*)(dout + OUT_V))[d] = v4;
    uint4 u;
    u.x=f2tf(k4.x); u.y=f2tf(k4.y); u.z=f2tf(k4.z); u.w=f2tf(k4.w);
    ((uint4*)g_kt)[d] = u;
    u.x=f2tf(v4.x); u.y=f2tf(v4.y); u.z=f2tf(v4.z); u.w=f2tf(v4.w);
    ((uint4*)g_vt)[d] = u;
}

// ---------------- tf32 GEMM core (cp.async, 2-stage) -------------------------
// BM=128, BN=128, BK=16, 256 thr, warp grid 2x4, warp tile 64x32, stride 20.
#define GST 20

__device__ __forceinline__
void gemm_core(const unsigned* __restrict__ AGLOB,
               const unsigned* __restrict__ BGLOB,
               int bm, int nrow0, float acc[4][4][4])
{
    __shared__ __align__(16) unsigned sAB[4*128*GST];
    unsigned* Asm[2] = { sAB,             sAB + 128*GST   };
    unsigned* Bsm[2] = { sAB + 2*128*GST, sAB + 3*128*GST };
    unsigned aAddr[2], bAddr[2];
    aAddr[0] = (unsigned)__cvta_generic_to_shared(Asm[0]);
    aAddr[1] = (unsigned)__cvta_generic_to_shared(Asm[1]);
    bAddr[0] = (unsigned)__cvta_generic_to_shared(Bsm[0]);
    bAddr[1] = (unsigned)__cvta_generic_to_shared(Bsm[1]);

    int tid = threadIdx.x;
    int warp = tid >> 5, lane = tid & 31, g = lane >> 2, tig = lane & 3;
    int wm = (warp >> 2)*64, wn = (warp & 3)*32;
    int r0c = tid >> 2, c0c = (tid & 3)*4;
    int r1c = r0c + 64;

    auto issue = [&](int st, int k0) {
        CP16(aAddr[st] + (unsigned)((r0c*GST + c0c)*4),
             AGLOB + (size_t)(bm + r0c)*E + k0 + c0c);
        CP16(aAddr[st] + (unsigned)((r1c*GST + c0c)*4),
             AGLOB + (size_t)(bm + r1c)*E + k0 + c0c);
        CP16(bAddr[st] + (unsigned)((r0c*GST + c0c)*4),
             BGLOB + (size_t)(nrow0 + r0c)*E + k0 + c0c);
        CP16(bAddr[st] + (unsigned)((r1c*GST + c0c)*4),
             BGLOB + (size_t)(nrow0 + r1c)*E + k0 + c0c);
    };

    #pragma unroll
    for (int mt = 0; mt < 4; mt++)
        #pragma unroll
        for (int nt = 0; nt < 4; nt++)
            #pragma unroll
            for (int i = 0; i < 4; i++) acc[mt][nt][i] = 0.f;

    issue(0, 0);  CPCOMMIT();
    issue(1, 16); CPCOMMIT();

    for (int kt = 0; kt < 64; kt++) {
        int cur = kt & 1;
        if (kt < 63) { CPWAIT(1); } else { CPWAIT(0); }
        __syncthreads();
        #pragma unroll
        for (int kh = 0; kh < 2; kh++) {
            int kb = kh*8;
            unsigned af[4][4], bf[4][2];
            #pragma unroll
            for (int mt = 0; mt < 4; mt++) {
                int r = wm + mt*16;
                af[mt][0] = Asm[cur][(r+g  )*GST + kb + tig];
                af[mt][1] = Asm[cur][(r+g+8)*GST + kb + tig];
                af[mt][2] = Asm[cur][(r+g  )*GST + kb + tig + 4];
                af[mt][3] = Asm[cur][(r+g+8)*GST + kb + tig + 4];
            }
            #pragma unroll
            for (int nt = 0; nt < 4; nt++) {
                int cidx = wn + nt*8 + g;
                bf[nt][0] = Bsm[cur][cidx*GST + kb + tig];
                bf[nt][1] = Bsm[cur][cidx*GST + kb + tig + 4];
            }
            #pragma unroll
            for (int mt = 0; mt < 4; mt++)
                #pragma unroll
                for (int nt = 0; nt < 4; nt++)
                    mma8(acc[mt][nt], af[mt][0], af[mt][1], af[mt][2],
                         af[mt][3], bf[nt][0], bf[nt][1]);
        }
        __syncthreads();
        if (kt + 2 < 64) { issue(cur, (kt+2)*16); CPCOMMIT(); }
    }
}

// ---------------- QKV projection ---------------------------------------------
__global__ __launch_bounds__(256, 2)
void gemm_qkv(const float* __restrict__ bq, const float* __restrict__ bk,
              const float* __restrict__ bv, float* __restrict__ dout)
{
    int bn = blockIdx.x*128, bm = blockIdx.y*128;
    int seg = bn >> 10;            // 0=Q 1=K 2=V
    int nrow0 = bn & (E-1);
    const unsigned* Bglob = (seg == 0) ? g_wqt : (seg == 1) ? g_wkt : g_wvt;
    const float*    bias  = (seg == 0) ? bq   : (seg == 1) ? bk    : bv;

    float acc[4][4][4];
    gemm_core(g_xt, Bglob, bm, nrow0, acc);

    int tid = threadIdx.x;
    int warp = tid >> 5, lane = tid & 31, g = lane >> 2, tig = lane & 3;
    int wm = (warp >> 2)*64, wn = (warp & 3)*32;

    #pragma unroll
    for (int mt = 0; mt < 4; mt++) {
        int m = bm + wm + mt*16 + g;
        #pragma unroll
        for (int nt = 0; nt < 4; nt++) {
            int nl = nrow0 + wn + nt*8 + 2*tig;
            float b0 = bias[nl], b1 = bias[nl+1];
            float v0 = acc[mt][nt][0] + b0, v1 = acc[mt][nt][1] + b1;
            float v2 = acc[mt][nt][2] + b0, v3 = acc[mt][nt][3] + b1;
            if (seg == 0) {
                uint2 u0; u0.x = f2tf(v0*0.125f); u0.y = f2tf(v1*0.125f);
                uint2 u1; u1.x = f2tf(v2*0.125f); u1.y = f2tf(v3*0.125f);
                *(uint2*)&g_q[(size_t)m*E + nl]     = u0;
                *(uint2*)&g_q[(size_t)(m+8)*E + nl] = u1;
            } else {
                float* fbase = dout + (seg == 1 ? OUT_K : OUT_V);
                unsigned* tbase = (seg == 1) ? g_kt : g_vt;
                int ba = m >> 9,      t0 = m & 511;
                int bb = (m+8) >> 9,  t1 = (m+8) & 511;
                size_t ra = ((size_t)(ba*KVL) + CL + t0)*E + nl;
                size_t rb = ((size_t)(bb*KVL) + CL + t1)*E + nl;
                *(float2*)&fbase[ra] = make_float2(v0, v1);
                *(float2*)&fbase[rb] = make_float2(v2, v3);
                uint2 u0; u0.x = f2tf(v0); u0.y = f2tf(v1);
                uint2 u1; u1.x = f2tf(v2); u1.y = f2tf(v3);
                *(uint2*)&tbase[ra] = u0;
                *(uint2*)&tbase[rb] = u1;
            }
        }
    }
}

// ---------------- output projection ------------------------------------------
__global__ __launch_bounds__(256, 2)
void gemm_out(const float* __restrict__ bo, float* __restrict__ dout)
{
    int bn = blockIdx.x*128, bm = blockIdx.y*128;

    float acc[4][4][4];
    gemm_core(g_ctx, g_wot, bm, bn, acc);

    int tid = threadIdx.x;
    int warp = tid >> 5, lane = tid & 31, g = lane >> 2, tig = lane & 3;
    int wm = (warp >> 2)*64, wn = (warp & 3)*32;

    #pragma unroll
    for (int mt = 0; mt < 4; mt++) {
        int m = bm + wm + mt*16 + g;
        #pragma unroll
        for (int nt = 0; nt < 4; nt++) {
            int n = bn + wn + nt*8 + 2*tig;
            float b0 = bo[n], b1 = bo[n+1];
            *(float2*)&dout[(size_t)m*E + n] =
                make_float2(acc[mt][nt][0] + b0, acc[mt][nt][1] + b1);
            *(float2*)&dout[(size_t)(m+8)*E + n] =
                make_float2(acc[mt][nt][2] + b0, acc[mt][nt][3] + b1);
        }
    }
}

// ---------------- flash attention (tf32, cp.async, shfl-P) -------------------
#define SWK(r,d) ((d) ^ ((((unsigned)(r))&7u)<<2))
#define SWV(r,d) ((d) ^ ((((unsigned)(r))&3u)<<3))

__global__ __launch_bounds__(128)
void attn(const float* __restrict__ amask)
{
    __shared__ __align__(16) unsigned sK[2][64*64];
    __shared__ __align__(16) unsigned sV[64*64];

    int qt = blockIdx.x, h = blockIdx.y, b = blockIdx.z;
    int tid  = threadIdx.x;
    int warp = tid >> 5, lane = tid & 31, g = lane >> 2, tig = lane & 3;
    int m0 = warp*16;

    unsigned kAddr[2], vAddr;
    kAddr[0] = (unsigned)__cvta_generic_to_shared(sK[0]);
    kAddr[1] = (unsigned)__cvta_generic_to_shared(sK[1]);
    vAddr    = (unsigned)__cvta_generic_to_shared(sV);

    const unsigned* kg = g_kt + ((size_t)b*KVL)*E + h*HD;
    const unsigned* vg = g_vt + ((size_t)b*KVL)*E + h*HD;

    auto issueK = [&](int tile, int st) {
        const unsigned* src = kg + (size_t)tile*64*E;
        #pragma unroll
        for (int i = 0; i < 8; i++) {
            int c = tid + i*128;
            int row = c >> 4, c4 = (c & 15)*4;
            CP16(kAddr[st] + (unsigned)((row*64 + SWK(row, c4))*4),
                 src + (size_t)row*E + c4);
        }
    };
    auto issueV = [&](int tile) {
        const unsigned* src = vg + (size_t)tile*64*E;
        #pragma unroll
        for (int i = 0; i < 8; i++) {
            int c = tid + i*128;
            int row = c >> 4, c4 = (c & 15)*4;
            CP16(vAddr + (unsigned)((row*64 + SWV(row, c4))*4),
                 src + (size_t)row*E + c4);
        }
    };

    unsigned qf[8][4];
    {
        const unsigned* qb = g_q + ((size_t)(b*QL + qt*64))*E + h*HD;
        #pragma unroll
        for (int kc = 0; kc < 8; kc++) {
            int kb = kc*8;
            qf[kc][0] = __ldg(qb + (size_t)(m0+g  )*E + kb + tig);
            qf[kc][1] = __ldg(qb + (size_t)(m0+g+8)*E + kb + tig);
            qf[kc][2] = __ldg(qb + (size_t)(m0+g  )*E + kb + tig + 4);
            qf[kc][3] = __ldg(qb + (size_t)(m0+g+8)*E + kb + tig + 4);
        }
    }

    float O[8][4];
    #pragma unroll
    for (int nt = 0; nt < 8; nt++)
        #pragma unroll
        for (int i = 0; i < 4; i++) O[nt][i] = 0.f;
    float mi0 = -1e30f, mi1 = -1e30f, li0 = 0.f, li1 = 0.f;

    int nkt = 25 + qt;
    issueK(0, 0); CPCOMMIT();

    for (int kt = 0; kt < nkt; kt++) {
        int cur = kt & 1;
        if (kt) __syncthreads();
        issueV(kt); CPCOMMIT();
        if (kt + 1 < nkt) {
            issueK(kt+1, 1-cur); CPCOMMIT();
            CPWAIT(2);
        } else {
            CPWAIT(1);
        }
        __syncthreads();

        // ---- S = (Q/8) K^T ----
        float s[8][4];
        #pragma unroll
        for (int nt = 0; nt < 8; nt++)
            #pragma unroll
            for (int i = 0; i < 4; i++) s[nt][i] = 0.f;
        #pragma unroll
        for (int kc = 0; kc < 8; kc++) {
            int kb = kc*8;
            #pragma unroll
            for (int nt = 0; nt < 8; nt++) {
                int col = nt*8 + g;
                unsigned b0 = sK[cur][col*64 + SWK(col, kb+tig)];
                unsigned b1 = sK[cur][col*64 + SWK(col, kb+tig+4)];
                mma8(s[nt], qf[kc][0], qf[kc][1], qf[kc][2], qf[kc][3], b0, b1);
            }
        }

        // ---- mask + online softmax ----
        int c0 = kt*64;
        const float* am = amask + (size_t)b*(CL+QL) + c0;
        bool last = (kt == nkt-1);
        #pragma unroll
        for (int nt = 0; nt < 8; nt++) {
            int j0 = nt*8 + 2*tig, j1 = j0 + 1;
            float a0 = __ldg(am + j0), a1 = __ldg(am + j1);
            s[nt][0] += a0; s[nt][1] += a1; s[nt][2] += a0; s[nt][3] += a1;
            if (last) {
                int r0 = m0 + g, r1 = r0 + 8;
                if (j0 > r0) s[nt][0] = -1e30f;
                if (j1 > r0) s[nt][1] = -1e30f;
                if (j0 > r1) s[nt][2] = -1e30f;
                if (j1 > r1) s[nt][3] = -1e30f;
            }
        }

        float mx0 = -1e30f, mx1 = -1e30f;
        #pragma unroll
        for (int nt = 0; nt < 8; nt++) {
            mx0 = fmaxf(mx0, fmaxf(s[nt][0], s[nt][1]));
            mx1 = fmaxf(mx1, fmaxf(s[nt][2], s[nt][3]));
        }
        mx0 = fmaxf(mx0, __shfl_xor_sync(0xffffffffu, mx0, 1));
        mx0 = fmaxf(mx0, __shfl_xor_sync(0xffffffffu, mx0, 2));
        mx1 = fmaxf(mx1, __shfl_xor_sync(0xffffffffu, mx1, 1));
        mx1 = fmaxf(mx1, __shfl_xor_sync(0xffffffffu, mx1, 2));

        float mn0 = fmaxf(mi0, mx0), mn1 = fmaxf(mi1, mx1);
        float cor0 = __expf(mi0 - mn0), cor1 = __expf(mi1 - mn1);
        mi0 = mn0; mi1 = mn1;

        float sum0 = 0.f, sum1 = 0.f;
        #pragma unroll
        for (int nt = 0; nt < 8; nt++) {
            s[nt][0] = __expf(s[nt][0] - mn0); sum0 += s[nt][0];
            s[nt][1] = __expf(s[nt][1] - mn0); sum0 += s[nt][1];
            s[nt][2] = __expf(s[nt][2] - mn1); sum1 += s[nt][2];
            s[nt][3] = __expf(s[nt][3] - mn1); sum1 += s[nt][3];
        }
        sum0 += __shfl_xor_sync(0xffffffffu, sum0, 1);
        sum0 += __shfl_xor_sync(0xffffffffu, sum0, 2);
        sum1 += __shfl_xor_sync(0xffffffffu, sum1, 1);
        sum1 += __shfl_xor_sync(0xffffffffu, sum1, 2);
        li0 = li0*cor0 + sum0;
        li1 = li1*cor1 + sum1;
        #pragma unroll
        for (int nt = 0; nt < 8; nt++) {
            O[nt][0] *= cor0; O[nt][1] *= cor0;
            O[nt][2] *= cor1; O[nt][3] *= cor1;
        }

        if (kt + 1 < nkt) { CPWAIT(1); } else { CPWAIT(0); }
        __syncthreads();

        // ---- O += P V  (P via cvt + shfl permutation; no smem round-trip) ----
        int l1 = (lane & 28) + (tig >> 1);
        int l2 = l1 + 2;
        bool odd = (tig & 1);
        #pragma unroll
        for (int kc = 0; kc < 8; kc++) {
            unsigned u0 = f2tf(s[kc][0]), u1 = f2tf(s[kc][1]);
            unsigned u2 = f2tf(s[kc][2]), u3 = f2tf(s[kc][3]);
            unsigned s00 = __shfl_sync(0xffffffffu, u0, l1);
            unsigned s01 = __shfl_sync(0xffffffffu, u1, l1);
            unsigned s02 = __shfl_sync(0xffffffffu, u2, l1);
            unsigned s03 = __shfl_sync(0xffffffffu, u3, l1);
            unsigned s10 = __shfl_sync(0xffffffffu, u0, l2);
            unsigned s11 = __shfl_sync(0xffffffffu, u1, l2);
            unsigned s12 = __shfl_sync(0xffffffffu, u2, l2);
            unsigned s13 = __shfl_sync(0xffffffffu, u3, l2);
            unsigned a0 = odd ? s01 : s00;
            unsigned a1 = odd ? s03 : s02;
            unsigned a2 = odd ? s11 : s10;
            unsigned a3 = odd ? s13 : s12;
            int kb = kc*8;
            #pragma unroll
            for (int nt = 0; nt < 8; nt++) {
                int dcol = nt*8 + g;
                unsigned b0 = sV[(kb+tig  )*64 + SWV(kb+tig,   dcol)];
                unsigned b1 = sV[(kb+tig+4)*64 + SWV(kb+tig+4, dcol)];
                mma8(O[nt], a0, a1, a2, a3, b0, b1);
            }
        }
    }

    // ---- write ctx (tf32) ----
    float inv0 = 1.f/li0, inv1 = 1.f/li1;
    int r0 = b*QL + qt*64 + m0 + g;
    #pragma unroll
    for (int nt = 0; nt < 8; nt++) {
        int col = h*HD + nt*8 + 2*tig;
        uint2 u0; u0.x = f2tf(O[nt][0]*inv0); u0.y = f2tf(O[nt][1]*inv0);
        uint2 u1; u1.x = f2tf(O[nt][2]*inv1); u1.y = f2tf(O[nt][3]*inv1);
        *(uint2*)&g_ctx[(size_t)r0*E + col]     = u0;
        *(uint2*)&g_ctx[(size_t)(r0+8)*E + col] = u1;
    }
}

// ---------------- launch ----------------------------------------------------
extern "C" void kernel_launch(void* const* d_in, const int* in_sizes, int n_in,
                              void* d_out, int out_size)
{
    const float* X     = (const float*)d_in[0];
    const float* amask = (const float*)d_in[1];
    const float* kc    = (const float*)d_in[2];
    const float* vc    = (const float*)d_in[3];
    const float* Wq    = (const float*)d_in[4];
    const float* bq    = (const float*)d_in[5];
    const float* Wk    = (const float*)d_in[6];
    const float* bk    = (const float*)d_in[7];
    const float* Wv    = (const float*)d_in[8];
    const float* bv    = (const float*)d_in[9];
    const float* Wo    = (const float*)d_in[10];
    const float* bo    = (const float*)d_in[11];
    float* out = (float*)d_out;

    convert_tf32<<<6144, 256>>>((const float4*)X, (const float4*)Wq,
                                (const float4*)Wk, (const float4*)Wv,
                                (const float4*)Wo);
    {
        int total = BZ*CL*E/4;
        copy_cache<<<(total + 255)/256, 256>>>((const float4*)kc,
                                               (const float4*)vc, out);
    }
    {
        dim3 grid(3*E/128, MROWS/128);       // 24 x 16
        gemm_qkv<<<grid, 256>>>(bq, bk, bv, out);
    }
    {
        dim3 grid(QL/64, NH, BZ);            // 8 x 16 x 4
        attn<<<grid, 128>>>(amask);
    }
    {
        dim3 grid(E/128, MROWS/128);         // 8 x 16
        gemm_out<<<grid, 256>>>(bo, out);
    }
}